// round 10
// baseline (speedup 1.0000x reference)
#include <cuda_runtime.h>
#include <math.h>

#define NPART 32
#define NT    256
#define T0F   (-2.99573227355399099343f)   // logf(0.05)
#define T1F   ( 3.46573590279972654709f)   // logf(32)
#define HTF   ((T1F - T0F) / (float)(NT - 1))
#define INVHT ((float)(NT - 1) / (T1F - T0F))
#define LN2F  (0.69314718055994530942f)
#define FULLM 0xffffffffu

__device__ float4 g_cv[NT];   // value cubic per interval (c0,c1,c2,c3) in s
__device__ float4 g_cg[NT];   // force-coef cubic per interval; g = (dv/dd)/d

__device__ __forceinline__ float fast_tanh(float x) {
    float ax = fabsf(x);
    float e  = __expf(ax + ax);
    float t  = 1.0f - __fdividef(2.0f, e + 1.0f);
    return copysignf(t, x);
}

// ---------------------------------------------------------------------------
// Builder: block bn computes nodes 7*bn .. 7*bn+7 (one per warp; one-node
// overlap with next block), converts 7 intervals to monomial coefficients.
// 2nd-order forward AD w.r.t. t = log d.
// ---------------------------------------------------------------------------
__global__ void __launch_bounds__(256)
build_table(const float* __restrict__ gW1, const float* __restrict__ gb1,
            const float* __restrict__ gW2, const float* __restrict__ gb2,
            const float* __restrict__ gW3, const float* __restrict__ gb3)
{
    __shared__ float sW2T[64 * 64];                  // [jj][k]
    __shared__ float sW1[192], sb1[64], sb2[64], sW3[64];
    __shared__ float4 sh[8][16], shp[8][16], shpp[8][16];
    __shared__ float4 snode[8];                      // (v, v'_s, g, g'_s)
    const int tid = threadIdx.x, lane = tid & 31, wrp = tid >> 5;

    for (int idx = tid; idx < 4096; idx += 256) {
        int k = idx >> 6, jj = idx & 63;             // gW2 is [k][jj]
        sW2T[jj * 64 + k] = gW2[idx];
    }
    for (int k = tid; k < 192; k += 256) sW1[k] = gW1[k];
    for (int k = tid; k < 64; k += 256) {
        sb1[k] = gb1[k]; sb2[k] = gb2[k]; sW3[k] = gW3[k];
    }
    __syncthreads();

    const int base = blockIdx.x * 7;
    const int node = min(base + wrp, NT - 1);

    const float t  = T0F + node * HTF;
    const float d  = expf(t);
    const float f1 = d, f2 = 1.0f / d, f3 = f2 * f2;

    float* shs   = (float*)sh[wrp];
    float* shps  = (float*)shp[wrp];
    float* shpps = (float*)shpp[wrp];
    #pragma unroll
    for (int q = 0; q < 2; q++) {
        int k = lane + q * 32;
        float w0 = sW1[k], w1 = sW1[64 + k], w2 = sW1[128 + k];
        float z   = sb1[k] + w0 * f1 + w1 * f2 + w2 * f3;
        float zp  = w0 * f1 - w1 * f2 - 2.0f * w2 * f3;
        float zpp = w0 * f1 + w1 * f2 + 4.0f * w2 * f3;
        float h   = fast_tanh(z);
        float s2  = 1.0f - h * h;
        shs[k]   = h;
        shps[k]  = s2 * zp;
        shpps[k] = s2 * (zpp - 2.0f * h * zp * zp);
    }
    __syncwarp();

    const float4* wra = (const float4*)(&sW2T[lane * 64]);
    const float4* wrb = (const float4*)(&sW2T[(lane + 32) * 64]);
    float za = sb2[lane],      zap = 0.f, zapp = 0.f;
    float zb = sb2[lane + 32], zbp = 0.f, zbpp = 0.f;
    #pragma unroll
    for (int r = 0; r < 16; r++) {
        int rr = (r + lane) & 15;
        float4 h4 = sh[wrp][rr];
        float4 p4 = shp[wrp][rr];
        float4 s4 = shpp[wrp][rr];
        float4 wa = wra[rr];
        float4 wb = wrb[rr];
        za   = fmaf(wa.x, h4.x, fmaf(wa.y, h4.y, fmaf(wa.z, h4.z, fmaf(wa.w, h4.w, za))));
        zap  = fmaf(wa.x, p4.x, fmaf(wa.y, p4.y, fmaf(wa.z, p4.z, fmaf(wa.w, p4.w, zap))));
        zapp = fmaf(wa.x, s4.x, fmaf(wa.y, s4.y, fmaf(wa.z, s4.z, fmaf(wa.w, s4.w, zapp))));
        zb   = fmaf(wb.x, h4.x, fmaf(wb.y, h4.y, fmaf(wb.z, h4.z, fmaf(wb.w, h4.w, zb))));
        zbp  = fmaf(wb.x, p4.x, fmaf(wb.y, p4.y, fmaf(wb.z, p4.z, fmaf(wb.w, p4.w, zbp))));
        zbpp = fmaf(wb.x, s4.x, fmaf(wb.y, s4.y, fmaf(wb.z, s4.z, fmaf(wb.w, s4.w, zbpp))));
    }

    float ta = fast_tanh(za), tb = fast_tanh(zb);
    float sa = 1.0f - ta * ta, sb = 1.0f - tb * tb;
    float w3a = sW3[lane], w3b = sW3[lane + 32];
    float va   = fmaf(w3a, ta, w3b * tb);
    float vpa  = fmaf(w3a * sa, zap, w3b * sb * zbp);
    float vppa = fmaf(w3a * sa, zapp - 2.0f * ta * zap * zap,
                      w3b * sb * (zbpp - 2.0f * tb * zbp * zbp));

    #pragma unroll
    for (int off = 16; off; off >>= 1) {
        va   += __shfl_xor_sync(FULLM, va,   off);
        vpa  += __shfl_xor_sync(FULLM, vpa,  off);
        vppa += __shfl_xor_sync(FULLM, vppa, off);
    }
    if (lane == 0) {
        float v    = va + gb3[0];
        float em2t = f3;                             // e^{-2t}
        float g    = vpa * em2t;                     // (dv/dd)/d
        float gp   = (vppa - 2.0f * vpa) * em2t;     // dg/dt
        snode[wrp] = make_float4(v, vpa * HTF, g, gp * HTF);
    }
    __syncthreads();

    if (tid < 7) {
        int m = base + tid;
        if (m < NT - 1) {
            float4 n0 = snode[tid], n1 = snode[tid + 1];
            float dv = n1.x - n0.x;
            g_cv[m] = make_float4(n0.x, n0.y, 3.f * dv - 2.f * n0.y - n1.y,
                                  -2.f * dv + n0.y + n1.y);
            float dg = n1.z - n0.z;
            g_cg[m] = make_float4(n0.z, n0.w, 3.f * dg - 2.f * n0.w - n1.w,
                                  -2.f * dg + n0.w + n1.w);
        }
    }
}

// ---------------------------------------------------------------------------
// Forces: one warp per batch; lane l evaluates ALL 31 partners (each pair
// done from both sides — no reaction shuffles, minimal MIO ops per pair).
// ---------------------------------------------------------------------------
__device__ __forceinline__ void pair_eval(
    int k, int lane, float px, float py, float pz,
    const float4* __restrict__ scv, const float4* __restrict__ scg,
    float KL, float C0,
    float& fx, float& fy, float& fz, float& vacc)
{
    const int src = (lane + k) & 31;
    float qx = __shfl_sync(FULLM, px, src);
    float qy = __shfl_sync(FULLM, py, src);
    float qz = __shfl_sync(FULLM, pz, src);
    float rx = px - qx, ry = py - qy, rz = pz - qz;
    float d2 = fmaf(rx, rx, fmaf(ry, ry, rz * rz));

    float u = fmaf(__log2f(d2), KL, C0);
    u = fminf(fmaxf(u, 0.0f), (float)NT - 1.001f);
    int   i0 = (int)u;
    float s  = u - (float)i0;

    float4 cv = scv[i0];
    float4 cg = scg[i0];
    float v = fmaf(fmaf(fmaf(cv.w, s, cv.z), s, cv.y), s, cv.x);
    float g = fmaf(fmaf(fmaf(cg.w, s, cg.z), s, cg.y), s, cg.x);

    g = (d2 > 0.0025f) ? g : 0.0f;   // clipped: zero force

    fx = fmaf(-g, rx, fx);
    fy = fmaf(-g, ry, fy);
    fz = fmaf(-g, rz, fz);
    vacc += v;
}

__global__ void __launch_bounds__(128)
forces_kernel(const float* __restrict__ gpos, float* __restrict__ out, int B)
{
    __shared__ float4 scv[NT];   // 4 KB
    __shared__ float4 scg[NT];   // 4 KB
    const int tid  = threadIdx.x;
    const int lane = tid & 31;
    const int wrp  = tid >> 5;
    const int b = blockIdx.x * 4 + wrp;

    #pragma unroll
    for (int q = 0; q < NT / 128; q++) {
        scv[q * 128 + tid] = __ldg(&g_cv[q * 128 + tid]);
        scg[q * 128 + tid] = __ldg(&g_cg[q * 128 + tid]);
    }

    float px = 0.f, py = 0.f, pz = 0.f;
    if (b < B) {
        px = gpos[b * 96 + lane * 3 + 0];
        py = gpos[b * 96 + lane * 3 + 1];
        pz = gpos[b * 96 + lane * 3 + 2];
    }
    __syncthreads();
    if (b >= B) return;

    const float KL = 0.5f * LN2F * INVHT;   // u = (0.5*ln(d2) - T0) * INVHT
    const float C0 = -T0F * INVHT;

    float fx0 = 0.f, fy0 = 0.f, fz0 = 0.f, v0 = 0.f;
    float fx1 = 0.f, fy1 = 0.f, fz1 = 0.f, v1 = 0.f;

    // k = 1..31, two independent chains per loop body
    #pragma unroll
    for (int k = 1; k <= 29; k += 2) {
        pair_eval(k,     lane, px, py, pz, scv, scg, KL, C0, fx0, fy0, fz0, v0);
        pair_eval(k + 1, lane, px, py, pz, scv, scg, KL, C0, fx1, fy1, fz1, v1);
    }
    pair_eval(31, lane, px, py, pz, scv, scg, KL, C0, fx0, fy0, fz0, v0);

    out[b * 96 + lane * 3 + 0] = fx0 + fx1;
    out[b * 96 + lane * 3 + 1] = fy0 + fy1;
    out[b * 96 + lane * 3 + 2] = fz0 + fz1;

    float vloc = v0 + v1;                  // every pair counted twice
    #pragma unroll
    for (int off = 16; off; off >>= 1)
        vloc += __shfl_xor_sync(FULLM, vloc, off);
    if (lane == 0)
        out[(long long)B * 96 + b] = 0.5f * vloc;
}

extern "C" void kernel_launch(void* const* d_in, const int* in_sizes, int n_in,
                              void* d_out, int out_size)
{
    const float* pos = (const float*)d_in[0];
    const float* W1  = (const float*)d_in[1];
    const float* b1  = (const float*)d_in[2];
    const float* W2  = (const float*)d_in[3];
    const float* b2  = (const float*)d_in[4];
    const float* W3  = (const float*)d_in[5];
    const float* b3  = (const float*)d_in[6];
    float* out = (float*)d_out;
    const int B = in_sizes[0] / 96;

    build_table<<<(NT + 5) / 7, 256>>>(W1, b1, W2, b2, W3, b3);
    forces_kernel<<<(B + 3) / 4, 128>>>(pos, out, B);
}